// round 2
// baseline (speedup 1.0000x reference)
#include <cuda_runtime.h>
#include <math_constants.h>

// Problem constants
#define NPOS 65536   // 64 * 32 * 32 positions
#define DIM  64      // embedding dim
#define KCB  512     // codebook size
#define NCHW_ELEMS 4194304  // 64*64*32*32

// Scratch (allocation-free: __device__ globals)
__device__ int    g_idx[NPOS];
__device__ int    g_hist[KCB];
__device__ float  g_ne[KCB];        // ||e_k||^2 in fp32 (fp64-accumulated)
__device__ double g_partial[512];

// ---------------------------------------------------------------------------
// Kernel 0: init — zero histogram, precompute ||e_k||^2 (fp64 -> fp32)
// ---------------------------------------------------------------------------
__global__ void vq_init_kernel(const float* __restrict__ emb) {
    int t = threadIdx.x;
    if (t < KCB) {
        g_hist[t] = 0;
        double s = 0.0;
#pragma unroll
        for (int d = 0; d < DIM; ++d) {
            double v = (double)emb[t * DIM + d];
            s += v * v;
        }
        g_ne[t] = (float)s;
    }
}

// ---------------------------------------------------------------------------
// Kernel A: argmin via tiled fp32 GEMM + EMULATED reference rounding.
// Reference computes dist_k = fl32( fl32(nx + ne_k) - fl32(2*s_k) ) where
// nx=||x||^2 (binade-equivalence suffices), s_k = x.e_k. We reproduce those
// roundings with intrinsics (no FMA contraction) and take first-index argmin.
// Grid: 1024 blocks x 256 threads. Block = 64 positions x 512 codes.
// ---------------------------------------------------------------------------
__global__ __launch_bounds__(256) void vq_argmin_kernel(
    const float* __restrict__ x, const float* __restrict__ emb)
{
    __shared__ float Xs[64 * 64];      // [d][pos], d-major
    __shared__ float Es[64 * 65];      // [code][d], row pad 65 (conflict-free)
    __shared__ float xpart[4 * 64];    // partial ||x||^2
    __shared__ float xn[64];           // ||x_p||^2

    const int tid = threadIdx.x;
    const int posBase = blockIdx.x * 64;
    const int b  = posBase >> 10;       // 1024 positions per batch image
    const int hw = posBase & 1023;
    const float* xb = x + (size_t)b * 65536 + hw;  // + d*1024 + p

    // Load X tile: coalesced gmem (p contiguous), Xs[d*64+p]
#pragma unroll
    for (int it = 0; it < 16; ++it) {
        int j = it * 256 + tid;
        int d = j >> 6, p = j & 63;
        Xs[j] = xb[d * 1024 + p];
    }
    __syncthreads();

    // nx per position (any fp32 value in the right binade works)
    {
        int p = tid & 63, g = tid >> 6;       // g in 0..3, 16 d's each
        float s = 0.f;
#pragma unroll
        for (int j = 0; j < 16; ++j) {
            float v = Xs[(g * 16 + j) * 64 + p];   // lanes -> distinct banks
            s = fmaf(v, v, s);
        }
        xpart[g * 64 + p] = s;
    }
    __syncthreads();
    if (tid < 64) {
        xn[tid] = ((xpart[tid] + xpart[64 + tid]) + xpart[128 + tid]) + xpart[192 + tid];
    }

    const int ry = tid >> 5;   // warp id: positions ry*8 .. ry*8+7
    const int cx = tid & 31;   // lane:    codes cx and cx+32 within chunk

    float best[8];
    int   bidx[8];
#pragma unroll
    for (int i = 0; i < 8; ++i) { best[i] = CUDART_INF_F; bidx[i] = 0; }

    for (int ch = 0; ch < 8; ++ch) {
        __syncthreads();
        // Load E chunk (64 codes x 64 d): coalesced read, conflict-free STS
#pragma unroll
        for (int it = 0; it < 16; ++it) {
            int j  = it * 256 + tid;
            int cc = j >> 6, d = j & 63;
            Es[cc * 65 + d] = emb[(ch * 64 + cc) * DIM + d];
        }
        __syncthreads();

        float acc0[8], acc1[8];
#pragma unroll
        for (int i = 0; i < 8; ++i) { acc0[i] = 0.f; acc1[i] = 0.f; }

#pragma unroll
        for (int d = 0; d < 64; ++d) {
            // e: two scalar LDS, lanes hit 32 distinct banks (stride 65)
            float e0 = Es[cx * 65 + d];
            float e1 = Es[(cx + 32) * 65 + d];
            // x: broadcast LDS.128 (all lanes in warp share ry)
            const float4 a0 = *(const float4*)&Xs[d * 64 + ry * 8];
            const float4 a1 = *(const float4*)&Xs[d * 64 + ry * 8 + 4];
            float xv[8] = {a0.x, a0.y, a0.z, a0.w, a1.x, a1.y, a1.z, a1.w};
#pragma unroll
            for (int i = 0; i < 8; ++i) {
                acc0[i] = fmaf(xv[i], e0, acc0[i]);
                acc1[i] = fmaf(xv[i], e1, acc1[i]);
            }
        }

        const int k0 = ch * 64 + cx;
        const int k1 = k0 + 32;
        const float ne0 = g_ne[k0];
        const float ne1 = g_ne[k1];
#pragma unroll
        for (int i = 0; i < 8; ++i) {
            float nxp = xn[ry * 8 + i];
            // EXACT emulation of jax op order; _rn intrinsics block contraction
            float d0 = __fsub_rn(__fadd_rn(nxp, ne0), __fmul_rn(2.0f, acc0[i]));
            float d1 = __fsub_rn(__fadd_rn(nxp, ne1), __fmul_rn(2.0f, acc1[i]));
            // strict < with ascending k keeps FIRST min (jax argmin semantics)
            if (d0 < best[i]) { best[i] = d0; bidx[i] = k0; }
            if (d1 < best[i]) { best[i] = d1; bidx[i] = k1; }
        }
    }

    // Warp butterfly argmin per position (tie -> smaller index)
#pragma unroll
    for (int i = 0; i < 8; ++i) {
        float v = best[i];
        int   id = bidx[i];
#pragma unroll
        for (int off = 16; off > 0; off >>= 1) {
            float ov = __shfl_xor_sync(0xffffffffu, v, off);
            int   oi = __shfl_xor_sync(0xffffffffu, id, off);
            if (ov < v || (ov == v && oi < id)) { v = ov; id = oi; }
        }
        if (cx == 0) {
            int pos = posBase + ry * 8 + i;
            g_idx[pos] = id;
            atomicAdd(&g_hist[id], 1);  // integer atomics: deterministic
        }
    }
}

// ---------------------------------------------------------------------------
// Kernel B: gather + straight-through emulation + both layouts + loss partials.
// q_st = fl32(x + fl32(q - x))  (matches jax's x + stop_grad(q - x))
// Output layout: out[0]=loss, out[1..1+4194304)=NCHW q_st,
//                out[4194305]=perplexity, out[4194306..)=flat NHWC q_st.
// ---------------------------------------------------------------------------
__global__ __launch_bounds__(256) void vq_output_kernel(
    const float* __restrict__ x, const float* __restrict__ emb,
    float* __restrict__ out)
{
    __shared__ float qs[128 * 65];   // tile [pos][d], pad 65
    __shared__ int   ks[128];
    __shared__ double red[256];

    const int tid = threadIdx.x;
    const int posBase = blockIdx.x * 128;
    const int b  = posBase >> 10;
    const int hw = posBase & 1023;

    if (tid < 128) ks[tid] = g_idx[posBase + tid];
    __syncthreads();

    float* out_nchw = out + 1;
    float* out_flat = out + 2 + NCHW_ELEMS;

    // Pass 1 (pos-major): coalesced codebook gather into smem
#pragma unroll
    for (int it = 0; it < 32; ++it) {
        int j = it * 256 + tid;
        int p = j >> 6, d = j & 63;
        qs[p * 65 + d] = emb[ks[p] * DIM + d];   // consecutive d: coalesced
    }
    __syncthreads();

    // Pass 2 (d-major): coalesced x read, NCHW q_st write, loss accumulation;
    // store q_st back into the tile for pass 3.
    double lsum = 0.0;
#pragma unroll
    for (int it = 0; it < 32; ++it) {
        int j = it * 256 + tid;
        int d = j >> 7, p = j & 127;
        size_t g = (size_t)b * 65536 + (size_t)d * 1024 + hw + p;
        float q  = qs[p * 65 + d];          // pad 65 -> conflict-free
        float xv = x[g];
        float df  = __fsub_rn(q, xv);       // fl32(q - x)
        float qst = __fadd_rn(xv, df);      // fl32(x + (q - x))
        out_nchw[g] = qst;
        qs[p * 65 + d] = qst;
        float sq = __fmul_rn(df, df);       // reference squares in fp32
        lsum += (double)sq;
    }
    __syncthreads();

    // Pass 3 (pos-major): flat NHWC q_st write (coalesced)
#pragma unroll
    for (int it = 0; it < 32; ++it) {
        int j = it * 256 + tid;
        int p = j >> 6, d = j & 63;
        out_flat[(size_t)(posBase + p) * DIM + d] = qs[p * 65 + d];
    }

    red[tid] = lsum;
    __syncthreads();
    for (int s = 128; s > 0; s >>= 1) {
        if (tid < s) red[tid] += red[tid + s];
        __syncthreads();
    }
    if (tid == 0) g_partial[blockIdx.x] = red[0];
}

// ---------------------------------------------------------------------------
// Kernel C: deterministic finalize — loss scalar + perplexity.
// ---------------------------------------------------------------------------
__global__ void vq_finalize_kernel(float* __restrict__ out) {
    __shared__ double red[512];
    const int t = threadIdx.x;

    red[t] = g_partial[t];
    __syncthreads();
    for (int s = 256; s > 0; s >>= 1) {
        if (t < s) red[t] += red[t + s];
        __syncthreads();
    }
    if (t == 0) {
        // loss = q_latent + 0.25*e_latent; both equal mean((q-x)^2) forward
        double m = red[0] / (double)NCHW_ELEMS;
        out[0] = (float)(1.25 * m);
    }
    __syncthreads();

    double p = (double)g_hist[t] / 65536.0;
    red[t] = p * log(p + 1e-10);   // p==0 -> 0, no NaN
    __syncthreads();
    for (int s = 256; s > 0; s >>= 1) {
        if (t < s) red[t] += red[t + s];
        __syncthreads();
    }
    if (t == 0) {
        out[NCHW_ELEMS + 1] = (float)exp(-red[0]);  // perplexity
    }
}

// ---------------------------------------------------------------------------
extern "C" void kernel_launch(void* const* d_in, const int* in_sizes, int n_in,
                              void* d_out, int out_size) {
    const float* x   = (const float*)d_in[0];   // [64,64,32,32] f32 NCHW
    const float* emb = (const float*)d_in[1];   // [512,64] f32
    float* out = (float*)d_out;

    vq_init_kernel<<<1, 512>>>(emb);
    vq_argmin_kernel<<<1024, 256>>>(x, emb);
    vq_output_kernel<<<512, 256>>>(x, emb, out);
    vq_finalize_kernel<<<1, 512>>>(out);
}

// round 3
// speedup vs baseline: 1.3810x; 1.3810x over previous
#include <cuda_runtime.h>
#include <math_constants.h>

// Problem constants
#define NPOS 65536   // 64 * 32 * 32 positions
#define DIM  64      // embedding dim
#define KCB  512     // codebook size
#define NCHW_ELEMS 4194304  // 64*64*32*32

// Scratch (allocation-free: __device__ globals)
__device__ int   g_idx[NPOS];
__device__ int   g_hist[KCB];
__device__ float g_ne[KCB];        // ||e_k||^2 in fp32
__device__ float g_partial[512];

// Packed fp32x2 FMA (Blackwell): per-lane IEEE identical to scalar fmaf.
__device__ __forceinline__ void ffma2(unsigned long long& acc,
                                      unsigned long long a,
                                      unsigned long long b) {
    asm("fma.rn.f32x2 %0, %1, %2, %0;" : "+l"(acc) : "l"(a), "l"(b));
}
__device__ __forceinline__ unsigned long long dup2(float v) {
    unsigned long long r;
    asm("mov.b64 %0, {%1, %1};" : "=l"(r) : "f"(v));
    return r;
}
__device__ __forceinline__ void unpack2(unsigned long long p, float& lo, float& hi) {
    asm("mov.b64 {%0, %1}, %2;" : "=f"(lo), "=f"(hi) : "l"(p));
}

// ---------------------------------------------------------------------------
// Kernel 0: init — zero histogram, precompute ||e_k||^2 (fp32 fma chain)
// ---------------------------------------------------------------------------
__global__ void vq_init_kernel(const float* __restrict__ emb) {
    int t = threadIdx.x;
    if (t < KCB) {
        g_hist[t] = 0;
        const float4* e4 = (const float4*)(emb + t * DIM);
        float s = 0.f;
#pragma unroll
        for (int j = 0; j < 16; ++j) {
            float4 v = e4[j];
            s = fmaf(v.x, v.x, s);
            s = fmaf(v.y, v.y, s);
            s = fmaf(v.z, v.z, s);
            s = fmaf(v.w, v.w, s);
        }
        g_ne[t] = s;
    }
}

// ---------------------------------------------------------------------------
// Kernel A: argmin via tiled fp32 GEMM (FFMA2 mainloop) + EMULATED reference
// rounding: dist_k = fl32( fl32(nx + ne_k) - fl32(2*s_k) ), first-index argmin.
// Grid: 1024 blocks x 256 threads. Block = 64 positions x 512 codes.
// Warp ry handles positions ry*8..ry*8+7; lane cx handles codes cx, cx+32
// of each 64-code chunk. Positions are paired into f32x2 lanes.
// ---------------------------------------------------------------------------
__global__ __launch_bounds__(256) void vq_argmin_kernel(
    const float* __restrict__ x, const float* __restrict__ emb)
{
    __shared__ float Xs[64 * 64];      // [d][pos], d-major (pairs adjacent)
    __shared__ float Es[64 * 65];      // [code][d], row pad 65 (conflict-free)
    __shared__ float xpart[4 * 64];
    __shared__ float xn[64];           // ||x_p||^2 (binade-correct suffices)

    const int tid = threadIdx.x;
    const int posBase = blockIdx.x * 64;
    const int b  = posBase >> 10;       // 1024 positions per batch image
    const int hw = posBase & 1023;
    const float* xb = x + (size_t)b * 65536 + hw;  // + d*1024 + p

    // Load X tile: coalesced gmem (p contiguous), Xs[d*64+p]
#pragma unroll
    for (int it = 0; it < 16; ++it) {
        int j = it * 256 + tid;
        int d = j >> 6, p = j & 63;
        Xs[j] = xb[d * 1024 + p];
    }
    __syncthreads();

    // nx per position
    {
        int p = tid & 63, g = tid >> 6;
        float s = 0.f;
#pragma unroll
        for (int j = 0; j < 16; ++j) {
            float v = Xs[(g * 16 + j) * 64 + p];
            s = fmaf(v, v, s);
        }
        xpart[g * 64 + p] = s;
    }
    __syncthreads();
    if (tid < 64) {
        xn[tid] = ((xpart[tid] + xpart[64 + tid]) + xpart[128 + tid]) + xpart[192 + tid];
    }

    const int ry = tid >> 5;
    const int cx = tid & 31;

    float best[8];
    int   bidx[8];
#pragma unroll
    for (int i = 0; i < 8; ++i) { best[i] = CUDART_INF_F; bidx[i] = 0; }

    for (int ch = 0; ch < 8; ++ch) {
        __syncthreads();
#pragma unroll
        for (int it = 0; it < 16; ++it) {
            int j  = it * 256 + tid;
            int cc = j >> 6, d = j & 63;
            Es[cc * 65 + d] = emb[(ch * 64 + cc) * DIM + d];
        }
        __syncthreads();

        // acc[j] packs positions (2j, 2j+1)
        unsigned long long acc0[4] = {0ull, 0ull, 0ull, 0ull};
        unsigned long long acc1[4] = {0ull, 0ull, 0ull, 0ull};

#pragma unroll
        for (int d = 0; d < 64; ++d) {
            float e0 = Es[cx * 65 + d];          // stride-65: conflict-free
            float e1 = Es[(cx + 32) * 65 + d];
            unsigned long long e0p = dup2(e0);
            unsigned long long e1p = dup2(e1);
            // broadcast 128-bit shared loads: 4 packed position-pairs
            const ulonglong2 a0 = *(const ulonglong2*)&Xs[d * 64 + ry * 8];
            const ulonglong2 a1 = *(const ulonglong2*)&Xs[d * 64 + ry * 8 + 4];
            ffma2(acc0[0], a0.x, e0p);  ffma2(acc1[0], a0.x, e1p);
            ffma2(acc0[1], a0.y, e0p);  ffma2(acc1[1], a0.y, e1p);
            ffma2(acc0[2], a1.x, e0p);  ffma2(acc1[2], a1.x, e1p);
            ffma2(acc0[3], a1.y, e0p);  ffma2(acc1[3], a1.y, e1p);
        }

        const int k0 = ch * 64 + cx;
        const int k1 = k0 + 32;
        const float ne0 = g_ne[k0];
        const float ne1 = g_ne[k1];
#pragma unroll
        for (int j = 0; j < 4; ++j) {
            float s0a, s0b, s1a, s1b;
            unpack2(acc0[j], s0a, s0b);
            unpack2(acc1[j], s1a, s1b);
            float nxa = xn[ry * 8 + 2 * j];
            float nxb = xn[ry * 8 + 2 * j + 1];
            // exact emulation of jax op order; _rn blocks contraction
            float d0a = __fsub_rn(__fadd_rn(nxa, ne0), __fmul_rn(2.0f, s0a));
            float d1a = __fsub_rn(__fadd_rn(nxa, ne1), __fmul_rn(2.0f, s1a));
            float d0b = __fsub_rn(__fadd_rn(nxb, ne0), __fmul_rn(2.0f, s0b));
            float d1b = __fsub_rn(__fadd_rn(nxb, ne1), __fmul_rn(2.0f, s1b));
            int ia = 2 * j, ib = 2 * j + 1;
            if (d0a < best[ia]) { best[ia] = d0a; bidx[ia] = k0; }
            if (d1a < best[ia]) { best[ia] = d1a; bidx[ia] = k1; }
            if (d0b < best[ib]) { best[ib] = d0b; bidx[ib] = k0; }
            if (d1b < best[ib]) { best[ib] = d1b; bidx[ib] = k1; }
        }
    }

    // Warp butterfly argmin per position (tie -> smaller index)
#pragma unroll
    for (int i = 0; i < 8; ++i) {
        float v = best[i];
        int   id = bidx[i];
#pragma unroll
        for (int off = 16; off > 0; off >>= 1) {
            float ov = __shfl_xor_sync(0xffffffffu, v, off);
            int   oi = __shfl_xor_sync(0xffffffffu, id, off);
            if (ov < v || (ov == v && oi < id)) { v = ov; id = oi; }
        }
        if (cx == 0) {
            int pos = posBase + ry * 8 + i;
            g_idx[pos] = id;
            atomicAdd(&g_hist[id], 1);
        }
    }
}

// ---------------------------------------------------------------------------
// Kernel B: gather + straight-through emulation + both layouts + loss partials.
// q_st = fl32(x + fl32(q - x)). All-fp32 reductions (pairwise-enough accuracy).
// Output layout: out[0]=loss, out[1..]=NCHW q_st, out[1+N]=perplexity,
//                out[2+N..]=flat NHWC q_st.
// ---------------------------------------------------------------------------
__global__ __launch_bounds__(256) void vq_output_kernel(
    const float* __restrict__ x, const float* __restrict__ emb,
    float* __restrict__ out)
{
    __shared__ float qs[128 * 65];   // tile [pos][d], pad 65
    __shared__ int   ks[128];
    __shared__ float red[256];

    const int tid = threadIdx.x;
    const int posBase = blockIdx.x * 128;
    const int b  = posBase >> 10;
    const int hw = posBase & 1023;

    if (tid < 128) ks[tid] = g_idx[posBase + tid];
    __syncthreads();

    float* out_nchw = out + 1;
    float* out_flat = out + 2 + NCHW_ELEMS;

    // Pass 1 (pos-major): coalesced codebook gather into smem
#pragma unroll
    for (int it = 0; it < 32; ++it) {
        int j = it * 256 + tid;
        int p = j >> 6, d = j & 63;
        qs[p * 65 + d] = emb[ks[p] * DIM + d];
    }
    __syncthreads();

    // Pass 2 (d-major): coalesced x read, NCHW q_st write, loss accumulation
    float lsum = 0.f;
#pragma unroll
    for (int it = 0; it < 32; ++it) {
        int j = it * 256 + tid;
        int d = j >> 7, p = j & 127;
        size_t g = (size_t)b * 65536 + (size_t)d * 1024 + hw + p;
        float q  = qs[p * 65 + d];
        float xv = x[g];
        float df  = __fsub_rn(q, xv);       // fl32(q - x)
        float qst = __fadd_rn(xv, df);      // fl32(x + (q - x))
        out_nchw[g] = qst;
        qs[p * 65 + d] = qst;
        lsum = fmaf(df, df, lsum);
    }
    __syncthreads();

    // Pass 3 (pos-major): flat NHWC q_st write (coalesced)
#pragma unroll
    for (int it = 0; it < 32; ++it) {
        int j = it * 256 + tid;
        int p = j >> 6, d = j & 63;
        out_flat[(size_t)(posBase + p) * DIM + d] = qs[p * 65 + d];
    }

    red[tid] = lsum;
    __syncthreads();
    for (int s = 128; s > 0; s >>= 1) {
        if (tid < s) red[tid] += red[tid + s];
        __syncthreads();
    }
    if (tid == 0) g_partial[blockIdx.x] = red[0];
}

// ---------------------------------------------------------------------------
// Kernel C: deterministic finalize — loss scalar + perplexity (all fp32).
// ---------------------------------------------------------------------------
__global__ void vq_finalize_kernel(float* __restrict__ out) {
    __shared__ float red[512];
    const int t = threadIdx.x;

    red[t] = g_partial[t];
    __syncthreads();
    for (int s = 256; s > 0; s >>= 1) {
        if (t < s) red[t] += red[t + s];
        __syncthreads();
    }
    if (t == 0) {
        out[0] = 1.25f * (red[0] / (float)NCHW_ELEMS);
    }
    __syncthreads();

    float p = (float)g_hist[t] * (1.0f / 65536.0f);
    red[t] = p * logf(p + 1e-10f);
    __syncthreads();
    for (int s = 256; s > 0; s >>= 1) {
        if (t < s) red[t] += red[t + s];
        __syncthreads();
    }
    if (t == 0) {
        out[NCHW_ELEMS + 1] = expf(-red[0]);
    }
}

// ---------------------------------------------------------------------------
extern "C" void kernel_launch(void* const* d_in, const int* in_sizes, int n_in,
                              void* d_out, int out_size) {
    const float* x   = (const float*)d_in[0];   // [64,64,32,32] f32 NCHW
    const float* emb = (const float*)d_in[1];   // [512,64] f32
    float* out = (float*)d_out;

    vq_init_kernel<<<1, 512>>>(emb);
    vq_argmin_kernel<<<1024, 256>>>(x, emb);
    vq_output_kernel<<<512, 256>>>(x, emb, out);
    vq_finalize_kernel<<<1, 512>>>(out);
}